// round 1
// baseline (speedup 1.0000x reference)
#include <cuda_runtime.h>

// Deformable conv2d: B=8, Cin=Cout=128, H=W=64, 3x3, stride 1, pad 1, DG=1.
// Fused bilinear-im2col + GEMM, fp32 with packed fma.rn.f32x2 (2 FMA/instr).
// Grid: 512 CTAs = (b, ho). Each CTA produces out[b, 0:128, ho, 0:64].

#define THREADS 256
static constexpr int CIN = 128, COUT = 128, H = 64, W = 64, KK = 9;
static constexpr int CCH = 4;             // channels per chunk
static constexpr int NCH = CIN / CCH;     // 32 chunks
static constexpr int TP  = 64;            // pixels per block (one output row)

__device__ __forceinline__ unsigned long long fma2(unsigned long long a,
                                                   unsigned long long b,
                                                   unsigned long long c) {
    unsigned long long d;
    asm("fma.rn.f32x2 %0, %1, %2, %3;" : "=l"(d) : "l"(a), "l"(b), "l"(c));
    return d;
}
__device__ __forceinline__ unsigned long long bcast2(float x) {
    unsigned long long r;
    asm("mov.b64 %0, {%1, %1};" : "=l"(r) : "f"(x));
    return r;
}
__device__ __forceinline__ void unpack2(unsigned long long v, float& lo, float& hi) {
    asm("mov.b64 {%0, %1}, %2;" : "=f"(lo), "=f"(hi) : "l"(v));
}

__global__ __launch_bounds__(THREADS, 2)
void deform_conv_kernel(const float* __restrict__ x,
                        const float* __restrict__ offs,
                        const float* __restrict__ wgt,
                        float* __restrict__ out) {
    // Tap metadata (channel-invariant): 9 taps x 64 pixels
    __shared__ __align__(16) int4   sIdx[KK * TP];          //  9216 B
    __shared__ __align__(16) float4 sWt [KK * TP];          //  9216 B
    __shared__ __align__(16) float  sCol[CCH * KK * TP];    //  9216 B
    __shared__ __align__(16) float  sW  [CCH * KK * COUT];  // 18432 B
                                                            // 46080 B total

    const int t  = threadIdx.x;
    const int b  = blockIdx.x >> 6;
    const int ho = blockIdx.x & 63;

    // ---------------- Phase 0: sampling metadata ----------------
    const float* ob = offs + b * (2 * KK) * (H * W);
    for (int i = t; i < KK * TP; i += THREADS) {
        int k = i >> 6, p = i & 63;
        float dy = ob[(2 * k)     * 4096 + ho * 64 + p];
        float dx = ob[(2 * k + 1) * 4096 + ho * 64 + p];
        float py = (float)(ho - 1 + k / 3) + dy;
        float px = (float)(p  - 1 + k % 3) + dx;
        float fy = floorf(py), fx = floorf(px);
        int y0 = (int)fy, x0 = (int)fx;
        float wy = py - fy, wx = px - fx;
        float wy1 = 1.f - wy, wx1 = 1.f - wx;
        float w00 = wy1 * wx1, w01 = wy1 * wx, w10 = wy * wx1, w11 = wy * wx;
        bool vy0 = (unsigned)y0       < (unsigned)H;
        bool vy1 = (unsigned)(y0 + 1) < (unsigned)H;
        bool vx0 = (unsigned)x0       < (unsigned)W;
        bool vx1 = (unsigned)(x0 + 1) < (unsigned)W;
        if (!(vy0 && vx0)) w00 = 0.f;
        if (!(vy0 && vx1)) w01 = 0.f;
        if (!(vy1 && vx0)) w10 = 0.f;
        if (!(vy1 && vx1)) w11 = 0.f;
        int cy0 = min(max(y0, 0), H - 1), cy1 = min(max(y0 + 1, 0), H - 1);
        int cx0 = min(max(x0, 0), W - 1), cx1 = min(max(x0 + 1, 0), W - 1);
        sIdx[i] = make_int4(cy0 * W + cx0, cy0 * W + cx1,
                            cy1 * W + cx0, cy1 * W + cx1);
        sWt[i]  = make_float4(w00, w01, w10, w11);
    }
    __syncthreads();

    const int lane = t & 31, warp = t >> 5;
    const int ci_g = warp >> 1;                 // gather: channel within chunk
    const int pg   = ((warp & 1) << 5) | lane;  // gather: pixel

    const int pp = t & 31;   // GEMM: pixel pair (pixels 2pp, 2pp+1)
    const int cg = t >> 5;   // GEMM: cout group (16 couts)

    unsigned long long acc[8][2];
    #pragma unroll
    for (int i = 0; i < 8; i++) { acc[i][0] = 0ull; acc[i][1] = 0ull; }

    for (int cc = 0; cc < NCH; cc++) {
        // ---- stage weight slice [4ch][9k][128cout] (transposed) ----
        #pragma unroll
        for (int r = 0; r < (CCH * KK * COUT) / THREADS; r++) {  // 18 iters
            int idx = r * THREADS + t;
            int co  = idx / (CCH * KK);
            int j   = idx - co * (CCH * KK);     // j == ci*9 + k
            sW[j * COUT + co] = wgt[co * (CIN * KK) + cc * (CCH * KK) + j];
        }
        // ---- bilinear gather: warp-pair per channel, lanes = pixels ----
        const float* xb = x + (b * CIN + cc * CCH + ci_g) * (H * W);
        #pragma unroll
        for (int k = 0; k < KK; k++) {
            int tap = k * 64 + pg;
            int4   id = sIdx[tap];
            float4 wv = sWt[tap];
            float v = wv.x * xb[id.x];
            v = fmaf(wv.y, xb[id.y], v);
            v = fmaf(wv.z, xb[id.z], v);
            v = fmaf(wv.w, xb[id.w], v);
            sCol[(ci_g * KK + k) * TP + pg] = v;
        }
        __syncthreads();
        // ---- GEMM: 16 couts x 2 pixels per thread, f32x2 over cout pairs ----
        #pragma unroll
        for (int ci = 0; ci < CCH; ci++) {
            unsigned long long cb[KK][2];
            #pragma unroll
            for (int k = 0; k < KK; k++) {
                float2 cv = *(const float2*)&sCol[(ci * KK + k) * TP + 2 * pp];
                cb[k][0] = bcast2(cv.x);
                cb[k][1] = bcast2(cv.y);
            }
            #pragma unroll
            for (int k = 0; k < KK; k++) {
                const unsigned long long* wp =
                    (const unsigned long long*)&sW[(ci * KK + k) * COUT + cg * 16];
                #pragma unroll
                for (int cp = 0; cp < 8; cp++) {
                    unsigned long long w2 = wp[cp];
                    acc[cp][0] = fma2(w2, cb[k][0], acc[cp][0]);
                    acc[cp][1] = fma2(w2, cb[k][1], acc[cp][1]);
                }
            }
        }
        __syncthreads();
    }

    // ---------------- epilogue ----------------
    float* orow = out + ((long)(b * COUT) * H + ho) * W;
    #pragma unroll
    for (int cp = 0; cp < 8; cp++) {
        int cout0 = cg * 16 + 2 * cp;
        float a0l, a0h, a1l, a1h;
        unpack2(acc[cp][0], a0l, a0h);   // pixel 2pp:   (cout0, cout0+1)
        unpack2(acc[cp][1], a1l, a1h);   // pixel 2pp+1: (cout0, cout0+1)
        *(float2*)&orow[(long)cout0       * (H * W) + 2 * pp] = make_float2(a0l, a1l);
        *(float2*)&orow[(long)(cout0 + 1) * (H * W) + 2 * pp] = make_float2(a0h, a1h);
    }
}

extern "C" void kernel_launch(void* const* d_in, const int* in_sizes, int n_in,
                              void* d_out, int out_size) {
    const float* x    = (const float*)d_in[0];
    const float* offs = (const float*)d_in[1];
    const float* wgt  = (const float*)d_in[2];
    deform_conv_kernel<<<512, THREADS>>>(x, offs, wgt, (float*)d_out);
}

// round 3
// speedup vs baseline: 2.7689x; 2.7689x over previous
#include <cuda_runtime.h>
#include <cstdint>

// Deformable conv2d B=8, Cin=Cout=128, H=W=64, 3x3 s1 p1 DG=1.
// smem-staged bilinear im2col + mma.sync tf32 HMMA GEMM.
// Grid: 512 CTAs = (b, ho); each produces out[b, 0:128, ho, 0:64].

#define THREADS 256
static constexpr int KTOT = 1152;

// smem layout (bytes)
static constexpr int OFF_MI = 0;        // int4[576]    9216
static constexpr int OFF_MW = 9216;     // float4[576]  9216
static constexpr int OFF_X  = 18432;    // 8ch x 12row x 68 floats = 26112
static constexpr int OFF_A  = 44544;    // 128 x 28 floats = 14336
static constexpr int OFF_B  = 58880;    // 24 x 72 floats  = 6912
static constexpr int SMEM_TOTAL = 65792;

static constexpr int XST = 68;          // x-window row stride (floats)
static constexpr int AST = 28;          // A tile row stride
static constexpr int BST = 72;          // B tile row stride

__device__ float g_wt[128 * KTOT];      // permuted, tf32-rounded weights

__device__ __forceinline__ uint32_t tf32c(float f) {
    uint32_t r;
    asm("cvt.rna.tf32.f32 %0, %1;" : "=r"(r) : "f"(f));
    return r;
}

__device__ __forceinline__ void mma8(float& d0, float& d1, float& d2, float& d3,
                                     uint32_t a0, uint32_t a1, uint32_t a2, uint32_t a3,
                                     uint32_t b0, uint32_t b1) {
    asm volatile(
        "mma.sync.aligned.m16n8k8.row.col.f32.tf32.tf32.f32 "
        "{%0,%1,%2,%3}, {%4,%5,%6,%7}, {%8,%9}, {%0,%1,%2,%3};"
        : "+f"(d0), "+f"(d1), "+f"(d2), "+f"(d3)
        : "r"(a0), "r"(a1), "r"(a2), "r"(a3), "r"(b0), "r"(b1));
}

// permute weight [co][ci*9+tap] -> [co][cg8*72 + tb*24 + ti*8 + cj], tf32-rounded
__global__ void wt_permute(const float* __restrict__ w) {
    int idx = blockIdx.x * 256 + threadIdx.x;
    if (idx >= 128 * KTOT) return;
    int co = idx / KTOT, r = idx % KTOT;
    int cg8 = r / 72, rem = r % 72;
    int tb = rem / 24, kl = rem % 24;
    int ti = kl >> 3, cj = kl & 7;
    int tap = tb * 3 + ti, ch = cg8 * 8 + cj;
    g_wt[idx] = __uint_as_float(tf32c(w[co * KTOT + ch * 9 + tap]));
}

__global__ __launch_bounds__(THREADS, 2)
void deform_conv_hmma(const float* __restrict__ x,
                      const float* __restrict__ offs,
                      float* __restrict__ out) {
    extern __shared__ char smem[];
    int4*     sMI = (int4*)(smem + OFF_MI);
    float4*   sMW = (float4*)(smem + OFF_MW);
    float*    sX  = (float*)(smem + OFF_X);
    float*    sAf = (float*)(smem + OFF_A);
    uint32_t* sAu = (uint32_t*)(smem + OFF_A);
    uint32_t* sBu = (uint32_t*)(smem + OFF_B);

    const int t = threadIdx.x, lane = t & 31, warp = t >> 5;
    const int b = blockIdx.x >> 6, ho = blockIdx.x & 63;
    const int lo = min(max(ho - 5, 0), 52);
    const float* xg = x + b * 524288;

    // ---- channel-invariant tap metadata: 9 taps x 64 px ----
    const float* ob = offs + b * 18 * 4096;
    for (int i = t; i < 576; i += THREADS) {
        int k = i >> 6, p = i & 63;
        float dy = ob[(2 * k) * 4096 + ho * 64 + p];
        float dx = ob[(2 * k + 1) * 4096 + ho * 64 + p];
        float py = (float)(ho - 1 + k / 3) + dy;
        float px = (float)(p  - 1 + k % 3) + dx;
        float fy = floorf(py), fx = floorf(px);
        int y0 = (int)fy, x0 = (int)fx;
        float wy = py - fy, wx = px - fx;
        float wy1 = 1.f - wy, wx1 = 1.f - wx;
        float w00 = wy1 * wx1, w01 = wy1 * wx, w10 = wy * wx1, w11 = wy * wx;
        bool vy0 = (unsigned)y0       < 64u, vy1 = (unsigned)(y0 + 1) < 64u;
        bool vx0 = (unsigned)x0       < 64u, vx1 = (unsigned)(x0 + 1) < 64u;
        if (!(vy0 && vx0)) w00 = 0.f;
        if (!(vy0 && vx1)) w01 = 0.f;
        if (!(vy1 && vx0)) w10 = 0.f;
        if (!(vy1 && vx1)) w11 = 0.f;
        int cy0 = min(max(y0, 0), 63), cy1 = min(max(y0 + 1, 0), 63);
        int cx0 = min(max(x0, 0), 63), cx1 = min(max(x0 + 1, 0), 63);
        sMI[i] = make_int4(cy0, cy1, cx0, cx1);
        sMW[i] = make_float4(w00, w01, w10, w11);
    }

    float acc[8][4];
    #pragma unroll
    for (int n = 0; n < 8; n++)
        #pragma unroll
        for (int c = 0; c < 4; c++) acc[n][c] = 0.f;

    const int g = lane >> 2, tq = lane & 3;

    for (int cg8 = 0; cg8 < 16; cg8++) {
        __syncthreads();   // sX free (prev gather done), sB free (prev mma done)
        // ---- stage 8-channel x window: rows [lo, lo+12) ----
        #pragma unroll
        for (int i = 0; i < 6; i++) {
            int idx = i * THREADS + t;          // 1536 float4
            int c = idx / 192, rr = idx - c * 192;
            int r = rr >> 4, w4 = rr & 15;
            float4 v = *(const float4*)(xg + (cg8 * 8 + c) * 4096 + (lo + r) * 64 + w4 * 4);
            *(float4*)(sX + (c * 12 + r) * XST + w4 * 4) = v;
        }
        __syncthreads();

        for (int tb = 0; tb < 3; tb++) {
            // ---- stage A tile: g_wt[co][kbase .. kbase+24) ----
            const int kbase = cg8 * 72 + tb * 24;
            #pragma unroll
            for (int i = 0; i < 3; i++) {
                int idx = i * THREADS + t;      // 768 float4
                int co = idx / 6, q = idx - co * 6;
                float4 v = *(const float4*)(g_wt + co * KTOT + kbase + q * 4);
                *(float4*)(sAf + co * AST + q * 4) = v;
            }
            // ---- gather B tile: 3 taps x 8 channels x 64 px ----
            if (t < 192) {
                int px = t & 63, ti = t >> 6;
                int tap = (tb * 3 + ti) * 64 + px;
                int4   mi = sMI[tap];
                float4 mw = sMW[tap];
                int wr0 = mi.x - lo, wr1 = mi.y - lo;
                bool in0 = (unsigned)wr0 < 12u, in1 = (unsigned)wr1 < 12u;
                const float* sTop = sX + wr0 * XST;
                const float* sBot = sX + wr1 * XST;
                #pragma unroll
                for (int cj = 0; cj < 8; cj++) {
                    float v00, v01, v10, v11;
                    if (in0 & in1) {
                        const float* pt = sTop + cj * (12 * XST);
                        const float* pb = sBot + cj * (12 * XST);
                        v00 = pt[mi.z]; v01 = pt[mi.w];
                        v10 = pb[mi.z]; v11 = pb[mi.w];
                    } else {  // rare: sample row outside staged window
                        const float* xp = xg + (cg8 * 8 + cj) * 4096;
                        const float* pt = sTop + cj * (12 * XST);
                        const float* pb = sBot + cj * (12 * XST);
                        v00 = in0 ? pt[mi.z] : xp[mi.x * 64 + mi.z];
                        v01 = in0 ? pt[mi.w] : xp[mi.x * 64 + mi.w];
                        v10 = in1 ? pb[mi.z] : xp[mi.y * 64 + mi.z];
                        v11 = in1 ? pb[mi.w] : xp[mi.y * 64 + mi.w];
                    }
                    float v = mw.x * v00;
                    v = fmaf(mw.y, v01, v);
                    v = fmaf(mw.z, v10, v);
                    v = fmaf(mw.w, v11, v);
                    sBu[(ti * 8 + cj) * BST + px] = tf32c(v);
                }
            }
            __syncthreads();
            // ---- HMMA: warp = 16-cout slab, 3 ksteps x 8 n-tiles ----
            #pragma unroll
            for (int ks = 0; ks < 3; ks++) {
                const uint32_t* ar = sAu + (warp * 16 + g) * AST + ks * 8 + tq;
                uint32_t a0 = ar[0];
                uint32_t a1 = ar[8 * AST];
                uint32_t a2 = ar[4];
                uint32_t a3 = ar[8 * AST + 4];
                const uint32_t* br = sBu + (ks * 8 + tq) * BST + g;
                #pragma unroll
                for (int nt = 0; nt < 8; nt++) {
                    uint32_t b0 = br[nt * 8];
                    uint32_t b1 = br[4 * BST + nt * 8];
                    mma8(acc[nt][0], acc[nt][1], acc[nt][2], acc[nt][3],
                         a0, a1, a2, a3, b0, b1);
                }
            }
            __syncthreads();   // protect sA/sB for next chunk
        }
    }

    // ---- epilogue: D frag (row=cout, col=px) -> global ----
    float* o = out + b * 524288 + (warp * 16 + g) * 4096 + ho * 64;
    #pragma unroll
    for (int nt = 0; nt < 8; nt++) {
        int px = nt * 8 + 2 * tq;
        *(float2*)(o + px)            = make_float2(acc[nt][0], acc[nt][1]);
        *(float2*)(o + 8 * 4096 + px) = make_float2(acc[nt][2], acc[nt][3]);
    }
}

extern "C" void kernel_launch(void* const* d_in, const int* in_sizes, int n_in,
                              void* d_out, int out_size) {
    const float* x    = (const float*)d_in[0];
    const float* offs = (const float*)d_in[1];
    const float* wgt  = (const float*)d_in[2];
    wt_permute<<<(128 * KTOT + 255) / 256, 256>>>(wgt);
    cudaFuncSetAttribute(deform_conv_hmma,
                         cudaFuncAttributeMaxDynamicSharedMemorySize, SMEM_TOTAL);
    deform_conv_hmma<<<512, THREADS, SMEM_TOTAL>>>(x, offs, (float*)d_out);
}

// round 4
// speedup vs baseline: 4.2234x; 1.5253x over previous
#include <cuda_runtime.h>
#include <cuda_fp16.h>
#include <cstdint>

// Deformable conv2d B=8, Cin=Cout=128, H=W=64, 3x3 s1 p1 DG=1.
// f16 HMMA (fp32 accum) + smem-staged bilinear im2col, 1-barrier pipeline.
// Grid: 512 CTAs = (b, ho).

#define THREADS 256
static constexpr int KTOT = 1152;
static constexpr int NSTEP = 48;        // 16 cg8 x 3 tb, 24 k each

// smem layout (bytes)
static constexpr int OFF_MI = 0;        // int4[576]    9216
static constexpr int OFF_MW = 9216;     // float4[576]  9216
static constexpr int OFF_X  = 18432;    // 2 x (8ch x 12r x 68) f32 = 52224
static constexpr int OFF_A  = 70656;    // 2 x 1536 u32 (128co x 12 half2) = 12288
static constexpr int OFF_B  = 82944;    // 2 x  864 u32 (12 k2 x 72)       = 6912
static constexpr int SMEM_TOTAL = 89856;

static constexpr int XST  = 68;         // x window row stride (floats)
static constexpr int XCH  = 12 * XST;   // 816 floats per channel
static constexpr int XWIN = 8 * XCH;    // 6528 floats per buffer
static constexpr int AST2 = 12;         // A row stride (half2) -> banks g*12+tq all distinct
static constexpr int BST2 = 72;         // B row stride (half2) -> banks 8tq+g+8nt distinct

// permuted weights: [slice=cg8*3+tb][co][k2=ti*4+j] as half2 {cj=2j, cj=2j+1}
__device__ uint32_t g_wt[NSTEP * 128 * 12];

__device__ __forceinline__ void mma_f16(float& d0, float& d1, float& d2, float& d3,
                                        uint32_t a0, uint32_t a1, uint32_t b0) {
    asm volatile(
        "mma.sync.aligned.m16n8k8.row.col.f32.f16.f16.f32 "
        "{%0,%1,%2,%3}, {%4,%5}, {%6}, {%0,%1,%2,%3};"
        : "+f"(d0), "+f"(d1), "+f"(d2), "+f"(d3)
        : "r"(a0), "r"(a1), "r"(b0));
}

__global__ void wt_permute(const float* __restrict__ w) {
    int idx = blockIdx.x * 256 + threadIdx.x;
    if (idx >= NSTEP * 128 * 12) return;
    int slice = idx / 1536, rem = idx % 1536;
    int co = rem / 12, kl = rem % 12;
    int ti = kl >> 2, j = kl & 3;
    int cg8 = slice / 3, tb = slice % 3;
    int tap = tb * 3 + ti, ch = cg8 * 8 + 2 * j;
    __half2 h = __floats2half2_rn(w[co * KTOT + ch * 9 + tap],
                                  w[co * KTOT + (ch + 1) * 9 + tap]);
    g_wt[idx] = *(uint32_t*)&h;
}

__global__ __launch_bounds__(THREADS, 2)
void deform_conv_f16(const float* __restrict__ x,
                     const float* __restrict__ offs,
                     float* __restrict__ out) {
    extern __shared__ char smem[];
    int4*     sMI = (int4*)(smem + OFF_MI);
    float4*   sMW = (float4*)(smem + OFF_MW);
    float*    sX  = (float*)(smem + OFF_X);
    uint32_t* sAu = (uint32_t*)(smem + OFF_A);
    uint32_t* sBu = (uint32_t*)(smem + OFF_B);

    const int t = threadIdx.x, lane = t & 31, warp = t >> 5;
    const int b = blockIdx.x >> 6, ho = blockIdx.x & 63;
    const int lo = min(max(ho - 5, 0), 52);
    const float* xg = x + b * 524288;

    // ---- tap metadata: 9 taps x 64 px (channel-invariant) ----
    const float* ob = offs + b * 18 * 4096;
    for (int i = t; i < 576; i += THREADS) {
        int k = i >> 6, p = i & 63;
        float dy = ob[(2 * k) * 4096 + ho * 64 + p];
        float dx = ob[(2 * k + 1) * 4096 + ho * 64 + p];
        float py = (float)(ho - 1 + k / 3) + dy;
        float px = (float)(p  - 1 + k % 3) + dx;
        float fy = floorf(py), fx = floorf(px);
        int y0 = (int)fy, x0 = (int)fx;
        float wy = py - fy, wx = px - fx;
        float wy1 = 1.f - wy, wx1 = 1.f - wx;
        float w00 = wy1 * wx1, w01 = wy1 * wx, w10 = wy * wx1, w11 = wy * wx;
        bool vy0 = (unsigned)y0       < 64u, vy1 = (unsigned)(y0 + 1) < 64u;
        bool vx0 = (unsigned)x0       < 64u, vx1 = (unsigned)(x0 + 1) < 64u;
        if (!(vy0 && vx0)) w00 = 0.f;
        if (!(vy0 && vx1)) w01 = 0.f;
        if (!(vy1 && vx0)) w10 = 0.f;
        if (!(vy1 && vx1)) w11 = 0.f;
        int cy0 = min(max(y0, 0), 63), cy1 = min(max(y0 + 1, 0), 63);
        int cx0 = min(max(x0, 0), 63), cx1 = min(max(x0 + 1, 0), 63);
        sMI[i] = make_int4(cy0, cy1, cx0, cx1);
        sMW[i] = make_float4(w00, w01, w10, w11);
    }

    // ---- prologue: X window 0 (all threads) ----
    #pragma unroll
    for (int i = 0; i < 6; i++) {
        int idx = i * THREADS + t;                  // 1536 float4
        int c = idx / 192, rr = idx - c * 192;
        int r = rr >> 4, w4 = rr & 15;
        float4 v = *(const float4*)(xg + c * 4096 + (lo + r) * 64 + w4 * 4);
        *(float4*)(sX + (c * 12 + r) * XST + w4 * 4) = v;
    }
    __syncthreads();

    const int g = lane >> 2, tq = lane & 3;
    float acc[8][4];
    #pragma unroll
    for (int n = 0; n < 8; n++)
        #pragma unroll
        for (int c = 0; c < 4; c++) acc[n][c] = 0.f;

    // ---- producer for step 0 ----
    if (warp < 6) {
        // gather step 0 (tb=0, cg8=0) into B buf 0
        const int px = t & 63, ti = t >> 6;
        int tap = ti * 64 + px;
        int4   mi = sMI[tap];
        float4 mw = sMW[tap];
        int wr0 = mi.x - lo, wr1 = mi.y - lo;
        bool in0 = (unsigned)wr0 < 12u, in1 = (unsigned)wr1 < 12u;
        bool in01 = in0 && in1;
        const float* sTop = sX + wr0 * XST;
        const float* sBot = sX + wr1 * XST;
        #pragma unroll
        for (int jj = 0; jj < 4; jj++) {
            float vv[2];
            #pragma unroll
            for (int h = 0; h < 2; h++) {
                int cj = 2 * jj + h;
                const float* pt = sTop + cj * XCH;
                const float* pb = sBot + cj * XCH;
                float v00, v01, v10, v11;
                if (in01) {
                    v00 = pt[mi.z]; v01 = pt[mi.w];
                    v10 = pb[mi.z]; v11 = pb[mi.w];
                } else {
                    const float* xp = xg + cj * 4096;
                    v00 = in0 ? pt[mi.z] : xp[mi.x * 64 + mi.z];
                    v01 = in0 ? pt[mi.w] : xp[mi.x * 64 + mi.w];
                    v10 = in1 ? pb[mi.z] : xp[mi.y * 64 + mi.z];
                    v11 = in1 ? pb[mi.w] : xp[mi.y * 64 + mi.w];
                }
                float v = mw.x * v00;
                v = fmaf(mw.y, v01, v);
                v = fmaf(mw.z, v10, v);
                vv[h] = fmaf(mw.w, v11, v);
            }
            __half2 hh = __floats2half2_rn(vv[0], vv[1]);
            sBu[(ti * 4 + jj) * BST2 + px] = *(uint32_t*)&hh;
        }
    } else {
        // stage A(0)
        int t2 = t - 192;
        const uint4* srcA = (const uint4*)g_wt;
        uint4* dstA = (uint4*)sAu;
        #pragma unroll
        for (int j = 0; j < 6; j++) dstA[t2 + j * 64] = srcA[t2 + j * 64];
    }

    // ---- main pipeline ----
    for (int s = 0; s < NSTEP; s++) {
        __syncthreads();   // A(s), B(s), X window(s/3) ready

        // MMA step s: all warps, 3 k8 steps x 8 n-tiles
        {
            const uint32_t* aU = sAu + (s & 1) * 1536 + (warp * 16 + g) * AST2;
            const uint32_t* bB = sBu + (s & 1) * 864;
            #pragma unroll
            for (int ks = 0; ks < 3; ks++) {
                uint32_t a0 = aU[ks * 4 + tq];
                uint32_t a1 = aU[8 * AST2 + ks * 4 + tq];
                const uint32_t* bU = bB + (ks * 4 + tq) * BST2 + g;
                #pragma unroll
                for (int nt = 0; nt < 8; nt++)
                    mma_f16(acc[nt][0], acc[nt][1], acc[nt][2], acc[nt][3],
                            a0, a1, bU[nt * 8]);
            }
        }

        if (s == NSTEP - 1) break;
        const int sp = s + 1;
        const int pcg = sp / 3, ptb = sp - pcg * 3;

        if (warp < 6) {
            // gather step s+1 into B buf (sp&1) from X window (pcg&1)
            const float* xw = sX + (pcg & 1) * XWIN;
            uint32_t* bD = sBu + (sp & 1) * 864;
            const int px = t & 63, ti = t >> 6;
            int tap = (ptb * 3 + ti) * 64 + px;
            int4   mi = sMI[tap];
            float4 mw = sMW[tap];
            int wr0 = mi.x - lo, wr1 = mi.y - lo;
            bool in0 = (unsigned)wr0 < 12u, in1 = (unsigned)wr1 < 12u;
            bool in01 = in0 && in1;
            const float* sTop = xw + wr0 * XST;
            const float* sBot = xw + wr1 * XST;
            const float* xcb = xg + pcg * 8 * 4096;
            #pragma unroll
            for (int jj = 0; jj < 4; jj++) {
                float vv[2];
                #pragma unroll
                for (int h = 0; h < 2; h++) {
                    int cj = 2 * jj + h;
                    const float* pt = sTop + cj * XCH;
                    const float* pb = sBot + cj * XCH;
                    float v00, v01, v10, v11;
                    if (in01) {
                        v00 = pt[mi.z]; v01 = pt[mi.w];
                        v10 = pb[mi.z]; v11 = pb[mi.w];
                    } else {
                        const float* xp = xcb + cj * 4096;
                        v00 = in0 ? pt[mi.z] : xp[mi.x * 64 + mi.z];
                        v01 = in0 ? pt[mi.w] : xp[mi.x * 64 + mi.w];
                        v10 = in1 ? pb[mi.z] : xp[mi.y * 64 + mi.z];
                        v11 = in1 ? pb[mi.w] : xp[mi.y * 64 + mi.w];
                    }
                    float v = mw.x * v00;
                    v = fmaf(mw.y, v01, v);
                    v = fmaf(mw.z, v10, v);
                    vv[h] = fmaf(mw.w, v11, v);
                }
                __half2 hh = __floats2half2_rn(vv[0], vv[1]);
                bD[(ti * 4 + jj) * BST2 + px] = *(uint32_t*)&hh;
            }
        } else {
            int t2 = t - 192;
            // stage A(s+1)
            {
                const uint4* srcA = (const uint4*)g_wt + sp * 384;
                uint4* dstA = (uint4*)(sAu + (sp & 1) * 1536);
                #pragma unroll
                for (int j = 0; j < 6; j++) dstA[t2 + j * 64] = srcA[t2 + j * 64];
            }
            // stage half of next X window (chunks at tb 0 and 1 of each cg8)
            int s3q = s / 3, s3r = s - s3q * 3;
            if (s3r < 2 && s3q + 1 < 16) {
                const int c = s3q + 1;
                float* xwn = sX + (c & 1) * XWIN;
                const float* xcb = xg + c * 8 * 4096;
                #pragma unroll
                for (int j = 0; j < 12; j++) {
                    int idx = s3r * 768 + t2 + j * 64;   // 768 float4 per chunk
                    int ch = idx / 192, rr = idx - ch * 192;
                    int r = rr >> 4, w4 = rr & 15;
                    float4 v = *(const float4*)(xcb + ch * 4096 + (lo + r) * 64 + w4 * 4);
                    *(float4*)(xwn + (ch * 12 + r) * XST + w4 * 4) = v;
                }
            }
        }
    }

    // ---- epilogue: D[m=cout][n=px] -> global ----
    float* o = out + b * 524288 + (warp * 16 + g) * 4096 + ho * 64;
    #pragma unroll
    for (int nt = 0; nt < 8; nt++) {
        int px = nt * 8 + 2 * tq;
        *(float2*)(o + px)            = make_float2(acc[nt][0], acc[nt][1]);
        *(float2*)(o + 8 * 4096 + px) = make_float2(acc[nt][2], acc[nt][3]);
    }
}

extern "C" void kernel_launch(void* const* d_in, const int* in_sizes, int n_in,
                              void* d_out, int out_size) {
    const float* x    = (const float*)d_in[0];
    const float* offs = (const float*)d_in[1];
    const float* wgt  = (const float*)d_in[2];
    wt_permute<<<(NSTEP * 128 * 12 + 255) / 256, 256>>>(wgt);
    cudaFuncSetAttribute(deform_conv_f16,
                         cudaFuncAttributeMaxDynamicSharedMemorySize, SMEM_TOTAL);
    deform_conv_f16<<<512, THREADS, SMEM_TOTAL>>>(x, offs, (float*)d_out);
}

// round 5
// speedup vs baseline: 4.9109x; 1.1628x over previous
#include <cuda_runtime.h>
#include <cuda_fp16.h>
#include <cstdint>

// Deformable conv2d B=8, Cin=Cout=128, H=W=64, 3x3 s1 p1 DG=1.
// f16 HMMA (fp32 accum), pair-interleaved fp16 X window (1 LDS per corner-pair),
// frag-ordered weight LDG (no A smem), 1-barrier pipeline. Grid: 512 = (b, ho).

#define THREADS 256
static constexpr int KTOT = 1152;
static constexpr int NSTEP = 48;        // 16 cg8 x 3 tb

// smem layout (bytes)
static constexpr int OFF_MI = 0;        // int4[576]    9216
static constexpr int OFF_MW = 9216;     // float4[576]  9216
static constexpr int OFF_X  = 18432;    // 2 x (8ch x 12r x 68 u32) = 52224
static constexpr int OFF_B  = 70656;    // 2 x 864 u32 = 6912
static constexpr int SMEM_TOTAL = 77568;

static constexpr int XST2  = 68;        // X row stride (u32 slots); 65 used
static constexpr int XCH2  = 12 * XST2; // 816
static constexpr int XWIN2 = 8 * XCH2;  // 6528 u32 per buffer
static constexpr int BST2  = 72;        // B row stride (u32)

// frag-ordered fp16 weights: [(slice*3+ks)*128 + co][tq], half2 = (ch even, ch odd)
__device__ uint32_t g_wtF[NSTEP * 3 * 128 * 4];

__device__ __forceinline__ void mma_f16(float* d, uint32_t a0, uint32_t a1,
                                        uint32_t b0) {
    asm volatile(
        "mma.sync.aligned.m16n8k8.row.col.f32.f16.f16.f32 "
        "{%0,%1,%2,%3}, {%4,%5}, {%6}, {%0,%1,%2,%3};"
        : "+f"(d[0]), "+f"(d[1]), "+f"(d[2]), "+f"(d[3])
        : "r"(a0), "r"(a1), "r"(b0));
}
__device__ __forceinline__ uint32_t h2u(__half2 h) { return *(uint32_t*)&h; }

__global__ void wt_permute(const float* __restrict__ w) {
    int idx = blockIdx.x * 256 + threadIdx.x;
    if (idx >= NSTEP * 3 * 128 * 4) return;
    int tq = idx & 3, co = (idx >> 2) & 127, rest = idx >> 9;
    int ks = rest % 3, slice = rest / 3;
    int cg8 = slice / 3, tb = slice % 3;
    int tap = tb * 3 + ks, ch0 = cg8 * 8 + 2 * tq;
    g_wtF[idx] = h2u(__floats2half2_rn(w[co * KTOT + ch0 * 9 + tap],
                                       w[co * KTOT + (ch0 + 1) * 9 + tap]));
}

// stage one float4 of an X window as interleaved half2 pairs PS[s]=(x[s-1],x[s])
__device__ __forceinline__ void stage_unit(uint32_t* xw, const float* xcb,
                                           int idx, int lo) {
    int ch = idx / 192, rr = idx - ch * 192;
    int r = rr >> 4, w4 = rr & 15;
    float4 f = *(const float4*)(xcb + ch * 4096 + (lo + r) * 64 + w4 * 4);
    float prev = __shfl_up_sync(0xffffffffu, f.w, 1);
    uint32_t* dst = xw + ch * XCH2 + r * XST2 + 4 * w4;
    *(uint4*)dst = make_uint4(h2u(__floats2half2_rn(prev, f.x)),
                              h2u(__floats2half2_rn(f.x, f.y)),
                              h2u(__floats2half2_rn(f.y, f.z)),
                              h2u(__floats2half2_rn(f.z, f.w)));
    if (w4 == 15) dst[4] = h2u(__floats2half2_rn(f.w, 0.f));
}

// gather one (tap,px) over 8 channels into B tile
__device__ __forceinline__ void gather_unit(const uint32_t* xw, const float* xcb,
                                            uint32_t* bD, const int4* sMI,
                                            const float4* sMW, int t, int ptb,
                                            int lo) {
    const int px = t & 63, ti = t >> 6;
    int tap = (ptb * 3 + ti) * 64 + px;
    int4   mi = sMI[tap];
    float4 mw = sMW[tap];
    int wr0 = mi.x - lo, wr1 = mi.y 
- lo;
    bool in0 = (unsigned)wr0 < 12u, in1 = (unsigned)wr1 < 12u;
    int wr0c = min(max(wr0, 0), 11), wr1c = min(max(wr1, 0), 11);
    const uint32_t* p0 = xw + wr0c * XST2 + mi.z;
    const uint32_t* p1 = xw + wr1c * XST2 + mi.z;
    uint32_t* bRow = bD + px;
    if (in0 && in1) {
        #pragma unroll
        for (int jj = 0; jj < 4; jj++) {
            float vv[2];
            #pragma unroll
            for (int h = 0; h < 2; h++) {
                int ch = 2 * jj + h;
                float2 t0 = __half22float2(*(const __half2*)&p0[ch * XCH2]);
                float2 t1 = __half22float2(*(const __half2*)&p1[ch * XCH2]);
                float v = mw.x * t0.x;
                v = fmaf(mw.y, t0.y, v);
                v = fmaf(mw.z, t1.x, v);
                vv[h] = fmaf(mw.w, t1.y, v);
            }
            bRow[(ti * 4 + jj) * BST2] = h2u(__floats2half2_rn(vv[0], vv[1]));
        }
    } else {  // rare: a sampled row falls outside the staged window
        int cx0 = min(max(mi.z - 1, 0), 63), cx1 = min(mi.z, 63);
        #pragma unroll
        for (int jj = 0; jj < 4; jj++) {
            float vv[2];
            #pragma unroll
            for (int h = 0; h < 2; h++) {
                int ch = 2 * jj + h;
                const float* xp = xcb + ch * 4096;
                float2 t0, t1;
                if (in0) t0 = __half22float2(*(const __half2*)&p0[ch * XCH2]);
                else     t0 = make_float2(xp[mi.x * 64 + cx0], xp[mi.x * 64 + cx1]);
                if (in1) t1 = __half22float2(*(const __half2*)&p1[ch * XCH2]);
                else     t1 = make_float2(xp[mi.y * 64 + cx0], xp[mi.y * 64 + cx1]);
                float v = mw.x * t0.x;
                v = fmaf(mw.y, t0.y, v);
                v = fmaf(mw.z, t1.x, v);
                vv[h] = fmaf(mw.w, t1.y, v);
            }
            bRow[(ti * 4 + jj) * BST2] = h2u(__floats2half2_rn(vv[0], vv[1]));
        }
    }
}

__global__ __launch_bounds__(THREADS, 2)
void deform_conv_f16p(const float* __restrict__ x,
                      const float* __restrict__ offs,
                      float* __restrict__ out) {
    extern __shared__ char smem[];
    int4*     sMI = (int4*)(smem + OFF_MI);
    float4*   sMW = (float4*)(smem + OFF_MW);
    uint32_t* sX  = (uint32_t*)(smem + OFF_X);
    uint32_t* sBu = (uint32_t*)(smem + OFF_B);

    const int t = threadIdx.x, lane = t & 31, warp = t >> 5;
    const int b = blockIdx.x >> 6, ho = blockIdx.x & 63;
    const int lo = min(max(ho - 5, 0), 52);
    const float* xg = x + b * 524288;

    // ---- tap metadata: 9 taps x 64 px (channel-invariant) ----
    const float* ob = offs + b * 18 * 4096;
    for (int i = t; i < 576; i += THREADS) {
        int k = i >> 6, p = i & 63;
        float dy = ob[(2 * k) * 4096 + ho * 64 + p];
        float dx = ob[(2 * k + 1) * 4096 + ho * 64 + p];
        float py = (float)(ho - 1 + k / 3) + dy;
        float px = (float)(p  - 1 + k % 3) + dx;
        float fy = floorf(py), fx = floorf(px);
        int y0 = (int)fy, x0 = (int)fx;
        float wy = py - fy, wx = px - fx;
        float wy1 = 1.f - wy, wx1 = 1.f - wx;
        float w00 = wy1 * wx1, w01 = wy1 * wx, w10 = wy * wx1, w11 = wy * wx;
        bool vy0 = (unsigned)y0       < 64u, vy1 = (unsigned)(y0 + 1) < 64u;
        bool vx0 = (unsigned)x0       < 64u, vx1 = (unsigned)(x0 + 1) < 64u;
        if (!(vy0 && vx0)) w00 = 0.f;
        if (!(vy0 && vx1)) w01 = 0.f;
        if (!(vy1 && vx0)) w10 = 0.f;
        if (!(vy1 && vx1)) w11 = 0.f;
        int cy0 = min(max(y0, 0), 63), cy1 = min(max(y0 + 1, 0), 63);
        int s   = min(max(x0, -1), 63) + 1;      // pair slot: PS[s]=(x[s-1],x[s])
        sMI[i] = make_int4(cy0, cy1, s, 0);
        sMW[i] = make_float4(w00, w01, w10, w11);
    }

    // ---- prologue: X window 0 (all threads) ----
    #pragma unroll
    for (int i = 0; i < 6; i++)
        stage_unit(sX, xg, i * THREADS + t, lo);
    __syncthreads();

    const int g = lane >> 2, tq = lane & 3;
    const int warpM = warp >> 1, warpN = warp & 1;
    float acc[2][4][4];
    #pragma unroll
    for (int m = 0; m < 2; m++)
        #pragma unroll
        for (int n = 0; n < 4; n++)
            #pragma unroll
            for (int c = 0; c < 4; c++) acc[m][n][c] = 0.f;

    // produce step 0 (gather only; A comes via LDG)
    if (warp < 6) gather_unit(sX, xg, sBu, sMI, sMW, t, 0, lo);

    // ---- main pipeline ----
    for (int s = 0; s < NSTEP; s++) {
        __syncthreads();   // B(s) + X window((s+?)/3) ready

        // MMA step s: 2 m-tiles x 4 n-tiles x 3 k8 steps
        {
            const uint32_t* bB = sBu + (s & 1) * 864 + warpN * 32 + g;
            #pragma unroll
            for (int ks = 0; ks < 3; ks++) {
                const uint32_t* ap =
                    g_wtF + (((s * 3 + ks) * 128 + warpM * 32) << 2) + lane;
                uint32_t a00 = __ldg(ap);
                uint32_t a01 = __ldg(ap + 32);
                uint32_t a10 = __ldg(ap + 64);
                uint32_t a11 = __ldg(ap + 96);
                const uint32_t* bU = bB + (ks * 4 + tq) * BST2;
                #pragma unroll
                for (int nt = 0; nt < 4; nt++) {
                    uint32_t b0 = bU[nt * 8];
                    mma_f16(acc[0][nt], a00, a01, b0);
                    mma_f16(acc[1][nt], a10, a11, b0);
                }
            }
        }

        if (s == NSTEP - 1) break;
        const int sp = s + 1;
        const int pcg = sp / 3, ptb = sp - pcg * 3;

        if (warp < 6) {
            gather_unit(sX + (pcg & 1) * XWIN2, xg + pcg * 8 * 4096,
                        sBu + (sp & 1) * 864, sMI, sMW, t, ptb, lo);
        } else {
            int s3q = s / 3, s3r = s - s3q * 3;
            if (s3r < 2 && s3q + 1 < 16) {
                const int c = s3q + 1;
                uint32_t* xwn = sX + (c & 1) * XWIN2;
                const float* xcb = xg + c * 8 * 4096;
                int t2 = t - 192;
                #pragma unroll
                for (int j = 0; j < 12; j++)
                    stage_unit(xwn, xcb, s3r * 768 + t2 + j * 64, lo);
            }
        }
    }

    // ---- epilogue: D[m=cout][n=px] -> global ----
    float* o = out + b * 524288 + ho * 64 + warpN * 32;
    #pragma unroll
    for (int mt = 0; mt < 2; mt++) {
        int row0 = warpM * 32 + mt * 16 + g;
        #pragma unroll
        for (int nt = 0; nt < 4; nt++) {
            int px = nt * 8 + 2 * tq;
            *(float2*)(o + row0 * 4096 + px) =
                make_float2(acc[mt][nt][0], acc[mt][nt][1]);
            *(float2*)(o + (row0 + 8) * 4096 + px) =
                make_float2(acc[mt][nt][2], acc[mt][nt][3]);
        }
    }
}

extern "C" void kernel_launch(void* const* d_in, const int* in_sizes, int n_in,
                              void* d_out, int out_size) {
    const float* x    = (const float*)d_in[0];
    const float* offs = (const float*)d_in[1];
    const float* wgt  = (const float*)d_in[2];
    wt_permute<<<(NSTEP * 3 * 128 * 4 + 255) / 256, 256>>>(wgt);
    cudaFuncSetAttribute(deform_conv_f16p,
                         cudaFuncAttributeMaxDynamicSharedMemorySize, SMEM_TOTAL);
    deform_conv_f16p<<<512, THREADS, SMEM_TOTAL>>>(x, offs, (float*)d_out);
}